// round 10
// baseline (speedup 1.0000x reference)
#include <cuda_runtime.h>
#include <cuda_fp16.h>
#include <cstdint>

#define BB 4
#define SS 2048
#define DD 1024
#define PP 1024

// ---------------- scratch (device globals; no allocation allowed) ----------
__device__ __half g_qkh[(size_t)BB * SS * 2048];        // rows: [q(1024) | k(1024)]
__device__ __half g_vt [(size_t)BB * PP * SS];          // per-batch (P, S)
__device__ float  g_s  [(size_t)BB * SS * SS];          // scores fp32 (pre-scaled)
__device__ __half g_ph [(size_t)BB * SS * SS];          // probs half
__device__ __half g_xh [(size_t)BB * SS * DD];          // x in half
__device__ __half g_wt [3][(size_t)PP * DD];            // Wq^T,Wk^T,Wv^T half (contig)

// ---------------- helpers ---------------------------------------------------
__device__ __forceinline__ uint32_t smem_u32(const void* p) {
    uint32_t a;
    asm("{ .reg .u64 t; cvta.to.shared.u64 t, %1; cvt.u32.u64 %0, t; }"
        : "=r"(a) : "l"(p));
    return a;
}

#define CP_ASYNC16(dst_u32, src_ptr) \
    asm volatile("cp.async.cg.shared.global [%0], [%1], 16;" \
                 :: "r"(dst_u32), "l"(src_ptr) : "memory")
#define CP_COMMIT() asm volatile("cp.async.commit_group;" ::: "memory")
#define CP_WAIT(n)  asm volatile("cp.async.wait_group %0;" :: "n"(n) : "memory")

#define LDSM_X4(r0, r1, r2, r3, addr) \
    asm volatile("ldmatrix.sync.aligned.m8n8.x4.shared.b16 {%0,%1,%2,%3}, [%4];" \
                 : "=r"(r0), "=r"(r1), "=r"(r2), "=r"(r3) : "r"(addr))

__device__ __forceinline__ void mma_f16(float* c, const uint32_t* a, const uint32_t* b) {
    asm volatile(
        "mma.sync.aligned.m16n8k16.row.col.f32.f16.f16.f32 "
        "{%0,%1,%2,%3}, {%4,%5,%6,%7}, {%8,%9}, {%0,%1,%2,%3};"
        : "+f"(c[0]), "+f"(c[1]), "+f"(c[2]), "+f"(c[3])
        : "r"(a[0]), "r"(a[1]), "r"(a[2]), "r"(a[3]), "r"(b[0]), "r"(b[1]));
}

// ---------------- conversion kernels ----------------------------------------
__global__ __launch_bounds__(256) void f2h(
    const float* __restrict__ in, __half* __restrict__ out, int n4)
{
    int i = blockIdx.x * 256 + threadIdx.x;
    if (i >= n4) return;
    float4 v = reinterpret_cast<const float4*>(in)[i];
    __half2 lo = __floats2half2_rn(v.x, v.y);
    __half2 hi = __floats2half2_rn(v.z, v.w);
    reinterpret_cast<uint2*>(out)[i] =
        make_uint2(*reinterpret_cast<uint32_t*>(&lo), *reinterpret_cast<uint32_t*>(&hi));
}

// (D,P) fp32 -> (P,D) half
__global__ __launch_bounds__(256) void transpose_h(
    const float* __restrict__ in, __half* __restrict__ out)
{
    __shared__ float t[32][33];
    int tx = threadIdx.x, ty = threadIdx.y;
    int x = blockIdx.x * 32 + tx;
    int y = blockIdx.y * 32 + ty;
#pragma unroll
    for (int j = 0; j < 32; j += 8)
        t[ty + j][tx] = in[(size_t)(y + j) * PP + x];
    __syncthreads();
    int x2 = blockIdx.y * 32 + tx;
    int y2 = blockIdx.x * 32 + ty;
#pragma unroll
    for (int j = 0; j < 32; j += 8)
        out[(size_t)(y2 + j) * DD + x2] = __float2half_rn(t[tx][ty + j]);
}

// ---------------- fp16 mma.sync NT GEMM, 256x128 CTA tile --------------------
// C[m,n] = sum_k A[m,k] * B[n,k]; A,B half row-major (leading dims in halves).
// MODE: 0 plain | 1 causal tile-skip + scale 1/32 on store | 2 K bound m0+256
// OUTH: 1 -> store half, 0 -> store float
#define BK 32
#define BM 256
#define BN 128
#define TILEA 20480            // 256 rows * 80 B
#define TILEB 10240            // 128 rows * 80 B
#define STAGEB 30720
#define SMEM_TOTAL 122880      // 4 stages

template <int MODE, int OUTH>
__global__ void __launch_bounds__(256, 1) gemm_nt_h(
    const __half* __restrict__ A, const __half* __restrict__ B, void* __restrict__ Cv,
    int lda, int ldb, int ldc, int K,
    long long sA, long long sB, long long sC)
{
    const int m0 = blockIdx.y * BM;
    const int n0 = blockIdx.x * BN;
    if (MODE == 1 && n0 >= m0 + BM) return;   // tile fully above diagonal

    extern __shared__ char smem[];
    const int bz = blockIdx.z;
    A += (long long)bz * sA;
    B += (long long)bz * sB;

    const int tid = threadIdx.x;
    const int lane = tid & 31;
    const int wid = tid >> 5;
    const int warp_m = wid & 3;        // 4 x 64 rows
    const int warp_n = wid >> 2;       // 2 x 64 cols
    const int g = lane >> 2;           // 0..7
    const int t = lane & 3;            // 0..3

    const uint32_t smb = smem_u32(smem);

    int kend = K;
    if (MODE == 2) { int lim = m0 + BM; kend = (lim < K) ? lim : K; }
    const int T = kend / BK;

    float acc[4][8][4];
#pragma unroll
    for (int mt = 0; mt < 4; mt++)
#pragma unroll
        for (int nt = 0; nt < 8; nt++)
#pragma unroll
            for (int i = 0; i < 4; i++) acc[mt][nt][i] = 0.f;

    // loader: A 1024 chunks (4/thr) + B 512 chunks (2/thr), 16B each
    const int lrow = tid >> 2;          // 0..63
    const int lc4  = tid & 3;
    auto load_tile = [&](int kt) {
        const int k0 = kt * BK;
        const uint32_t dA = smb + (kt & 3) * STAGEB;
        const uint32_t dB = dA + TILEA;
#pragma unroll
        for (int i = 0; i < 4; i++) {
            int row = lrow + i * 64;    // 0..255
            CP_ASYNC16(dA + (uint32_t)(row * 80 + lc4 * 16),
                       &A[(long long)(m0 + row) * lda + k0 + lc4 * 8]);
        }
#pragma unroll
        for (int i = 0; i < 2; i++) {
            int row = lrow + i * 64;    // 0..127
            CP_ASYNC16(dB + (uint32_t)(row * 80 + lc4 * 16),
                       &B[(long long)(n0 + row) * ldb + k0 + lc4 * 8]);
        }
    };

#pragma unroll
    for (int p = 0; p < 3; p++) { if (p < T) load_tile(p); CP_COMMIT(); }

    const int lr = lane & 15;
    const int lcb = (lane >> 4) * 16;
    const uint32_t aRow = (uint32_t)((warp_m * 64 + lr) * 80) + lcb;
    const uint32_t bRow = (uint32_t)((warp_n * 64 + lr) * 80) + lcb;

    for (int kt = 0; kt < T; kt++) {
        CP_WAIT(2);
        __syncthreads();
        if (kt + 3 < T) load_tile(kt + 3);
        CP_COMMIT();

        const uint32_t bufA = smb + (kt & 3) * STAGEB;
        const uint32_t bufB = bufA + TILEA;

#pragma unroll
        for (int ks = 0; ks < BK; ks += 16) {
            uint32_t a[4][4];
#pragma unroll
            for (int mt = 0; mt < 4; mt++)
                LDSM_X4(a[mt][0], a[mt][1], a[mt][2], a[mt][3],
                        bufA + aRow + (uint32_t)(mt * 16 * 80 + ks * 2));
            uint32_t b[8][2];
#pragma unroll
            for (int p = 0; p < 4; p++) {
                uint32_t r0, r1, r2, r3;
                LDSM_X4(r0, r1, r2, r3,
                        bufB + bRow + (uint32_t)(p * 16 * 80 + ks * 2));
                b[2*p][0] = r0; b[2*p+1][0] = r1;
                b[2*p][1] = r2; b[2*p+1][1] = r3;
            }
#pragma unroll
            for (int mt = 0; mt < 4; mt++)
#pragma unroll
                for (int nt = 0; nt < 8; nt++)
                    mma_f16(acc[mt][nt], a[mt], b[nt]);
        }
    }

    // ---- epilogue ----
    if (OUTH) {
        __half* C = reinterpret_cast<__half*>(Cv) + (long long)bz * sC;
#pragma unroll
        for (int mt = 0; mt < 4; mt++) {
            long long r = m0 + warp_m * 64 + mt * 16 + g;
#pragma unroll
            for (int nt = 0; nt < 8; nt++) {
                int c = n0 + warp_n * 64 + nt * 8 + t * 2;
                *reinterpret_cast<__half2*>(&C[r * ldc + c]) =
                    __floats2half2_rn(acc[mt][nt][0], acc[mt][nt][1]);
                *reinterpret_cast<__half2*>(&C[(r + 8) * ldc + c]) =
                    __floats2half2_rn(acc[mt][nt][2], acc[mt][nt][3]);
            }
        }
    } else {
        const float sc = (MODE == 1) ? 0.03125f : 1.0f;
        float* C = reinterpret_cast<float*>(Cv) + (long long)bz * sC;
#pragma unroll
        for (int mt = 0; mt < 4; mt++) {
            long long r = m0 + warp_m * 64 + mt * 16 + g;
#pragma unroll
            for (int nt = 0; nt < 8; nt++) {
                int c = n0 + warp_n * 64 + nt * 8 + t * 2;
                *reinterpret_cast<float2*>(&C[r * ldc + c]) =
                    make_float2(acc[mt][nt][0] * sc, acc[mt][nt][1] * sc);
                *reinterpret_cast<float2*>(&C[(r + 8) * ldc + c]) =
                    make_float2(acc[mt][nt][2] * sc, acc[mt][nt][3] * sc);
            }
        }
    }
}

// ---------------- register-resident causal softmax ---------------------------
// Scores already scaled by 1/32. Zero tail to 256-block boundary (context
// kend = m0+256 with 256-row tiles).
__global__ __launch_bounds__(256) void softmax_causal(
    const float* __restrict__ Sc, __half* __restrict__ Ph)
{
    const int r = blockIdx.x;
    const int b = r >> 11;
    const int s = r & 2047;
    const float* row = Sc + ((size_t)b * SS + s) * SS;
    __half* prow = Ph + ((size_t)b * SS + s) * SS;
    const int L = s + 1;
    const int Lpad = (L + 255) & ~255;
    const int tid = threadIdx.x;
    const int lane = tid & 31;
    const int wid = tid >> 5;
    __shared__ float red[8];

    float v[8];
    float mx = -1e30f;
#pragma unroll
    for (int j = 0; j < 2; j++) {
        int base = (tid + 256 * j) * 4;
        if (base < L) {
            float4 tv = *reinterpret_cast<const float4*>(row + base);
            v[j*4+0] = tv.x; v[j*4+1] = tv.y; v[j*4+2] = tv.z; v[j*4+3] = tv.w;
#pragma unroll
            for (int e = 0; e < 4; e++)
                if (base + e < L) mx = fmaxf(mx, v[j*4+e]);
        }
    }
#pragma unroll
    for (int o = 16; o > 0; o >>= 1)
        mx = fmaxf(mx, __shfl_xor_sync(0xffffffffu, mx, o));
    if (lane == 0) red[wid] = mx;
    __syncthreads();
    if (wid == 0) {
        float m = red[lane & 7];
#pragma unroll
        for (int o = 4; o > 0; o >>= 1)
            m = fmaxf(m, __shfl_xor_sync(0xffffffffu, m, o));
        if (lane == 0) red[0] = m;
    }
    __syncthreads();
    mx = red[0];

    float sum = 0.f;
#pragma unroll
    for (int j = 0; j < 2; j++) {
        int base = (tid + 256 * j) * 4;
        if (base < L) {
#pragma unroll
            for (int e = 0; e < 4; e++) {
                float ev = (base + e < L) ? __expf(v[j*4+e] - mx) : 0.f;
                v[j*4+e] = ev;
                sum += ev;
            }
        }
    }
#pragma unroll
    for (int o = 16; o > 0; o >>= 1)
        sum += __shfl_xor_sync(0xffffffffu, sum, o);
    __syncthreads();
    if (lane == 0) red[wid] = sum;
    __syncthreads();
    if (wid == 0) {
        float m = red[lane & 7];
#pragma unroll
        for (int o = 4; o > 0; o >>= 1)
            m += __shfl_xor_sync(0xffffffffu, m, o);
        if (lane == 0) red[0] = m;
    }
    __syncthreads();
    const float inv = 1.f / red[0];

#pragma unroll
    for (int j = 0; j < 2; j++) {
        int base = (tid + 256 * j) * 4;
        if (base < Lpad) {
            float e0 = (base < L) ? v[j*4+0] * inv : 0.f;
            float e1 = (base + 1 < L) ? v[j*4+1] * inv : 0.f;
            float e2 = (base + 2 < L) ? v[j*4+2] * inv : 0.f;
            float e3 = (base + 3 < L) ? v[j*4+3] * inv : 0.f;
            __half2 lo = __floats2half2_rn(e0, e1);
            __half2 hi = __floats2half2_rn(e2, e3);
            *reinterpret_cast<uint2*>(prow + base) =
                make_uint2(*reinterpret_cast<uint32_t*>(&lo),
                           *reinterpret_cast<uint32_t*>(&hi));
        }
    }
}

// ---------------- driver ----------------------------------------------------
extern "C" void kernel_launch(void* const* d_in, const int* in_sizes, int n_in,
                              void* d_out, int out_size)
{
    const float* x  = (const float*)d_in[0];
    const float* Wq = (const float*)d_in[1];
    const float* Wk = (const float*)d_in[2];
    const float* Wv = (const float*)d_in[3];
    float* out = (float*)d_out;

    __half *qkh, *vt, *ph, *xh, *wt;
    float* sc;
    cudaGetSymbolAddress((void**)&qkh, g_qkh);
    cudaGetSymbolAddress((void**)&vt,  g_vt);
    cudaGetSymbolAddress((void**)&sc,  g_s);
    cudaGetSymbolAddress((void**)&ph,  g_ph);
    cudaGetSymbolAddress((void**)&xh,  g_xh);
    cudaGetSymbolAddress((void**)&wt,  g_wt);
    __half* wvt = wt + (size_t)2 * PP * DD;

    cudaFuncSetAttribute(gemm_nt_h<0,1>, cudaFuncAttributeMaxDynamicSharedMemorySize, SMEM_TOTAL);
    cudaFuncSetAttribute(gemm_nt_h<1,0>, cudaFuncAttributeMaxDynamicSharedMemorySize, SMEM_TOTAL);
    cudaFuncSetAttribute(gemm_nt_h<2,0>, cudaFuncAttributeMaxDynamicSharedMemorySize, SMEM_TOTAL);

    // 0) conversions
    const int xn4 = (BB * SS * DD) / 4;
    f2h<<<(xn4 + 255) / 256, 256>>>(x, xh, xn4);
    dim3 tb(32, 8), tg(32, 32);
    transpose_h<<<tg, tb>>>(Wq, wt);
    transpose_h<<<tg, tb>>>(Wk, wt + (size_t)PP * DD);
    transpose_h<<<tg, tb>>>(Wv, wvt);

    const long long sSD  = (long long)SS * DD;
    const long long sPS  = (long long)PP * SS;
    const long long sSSq = (long long)SS * SS;
    const long long sQK  = (long long)SS * 2048;
    const long long sSP  = (long long)SS * PP;

    // 1) fused q|k: NT(xh, [Wq^T;Wk^T])  M=B*S, N=2048, K=D -> (B*S, 2048)
    dim3 gqk(2048 / BN, (BB * SS) / BM, 1);
    gemm_nt_h<0,1><<<gqk, 256, SMEM_TOTAL>>>(xh, wt, qkh, DD, DD, 2048, DD, 0, 0, 0);

    // 2) v^T per batch: NT(Wv^T, xh_b)  M=P, N=S, K=D
    dim3 gv(SS / BN, PP / BM, BB);
    gemm_nt_h<0,1><<<gv, 256, SMEM_TOTAL>>>(wvt, xh, vt, DD, DD, SS, DD, 0, sSD, sPS);

    // 3) scores: NT(q_b, k_b) via strided views of qkh; scale folded in
    dim3 gs(SS / BN, SS / BM, BB);
    gemm_nt_h<1,0><<<gs, 256, SMEM_TOTAL>>>(qkh, qkh + 1024, sc,
                                            2048, 2048, SS, PP, sQK, sQK, sSSq);

    // 4) softmax, half probs + zero tail to 256 boundary
    softmax_causal<<<BB * SS, 256>>>(sc, ph);

    // 5) context: NT(P_b, v^T_b)  M=S, N=P, K bounded at m0+256
    dim3 gc(PP / BN, SS / BM, BB);
    gemm_nt_h<2,0><<<gc, 256, SMEM_TOTAL>>>(ph, vt, out, SS, SS, PP, SS, sSSq, sPS, sSP);
}

// round 11
// speedup vs baseline: 1.0140x; 1.0140x over previous
#include <cuda_runtime.h>
#include <cuda_fp16.h>
#include <cstdint>

#define BB 4
#define SS 2048
#define DD 1024
#define PP 1024

// ---------------- scratch (device globals; no allocation allowed) ----------
__device__ __half g_qkh[(size_t)BB * SS * 2048];        // rows: [q(1024) | k(1024)]
__device__ __half g_vt [(size_t)BB * PP * SS];          // per-batch (P, S)
__device__ float  g_s  [(size_t)BB * SS * SS];          // scores fp32 (pre-scaled)
__device__ __half g_ph [(size_t)BB * SS * SS];          // probs half
__device__ __half g_xh [(size_t)BB * SS * DD];          // x in half
__device__ __half g_wt [3][(size_t)PP * DD];            // Wq^T,Wk^T,Wv^T half (contig)

// ---------------- helpers ---------------------------------------------------
__device__ __forceinline__ uint32_t smem_u32(const void* p) {
    uint32_t a;
    asm("{ .reg .u64 t; cvta.to.shared.u64 t, %1; cvt.u32.u64 %0, t; }"
        : "=r"(a) : "l"(p));
    return a;
}

#define CP_ASYNC16(dst_u32, src_ptr) \
    asm volatile("cp.async.cg.shared.global [%0], [%1], 16;" \
                 :: "r"(dst_u32), "l"(src_ptr) : "memory")
#define CP_COMMIT() asm volatile("cp.async.commit_group;" ::: "memory")
#define CP_WAIT(n)  asm volatile("cp.async.wait_group %0;" :: "n"(n) : "memory")

#define LDSM_X4(r0, r1, r2, r3, addr) \
    asm volatile("ldmatrix.sync.aligned.m8n8.x4.shared.b16 {%0,%1,%2,%3}, [%4];" \
                 : "=r"(r0), "=r"(r1), "=r"(r2), "=r"(r3) : "r"(addr))

__device__ __forceinline__ void mma_f16(float* c, const uint32_t* a, const uint32_t* b) {
    asm volatile(
        "mma.sync.aligned.m16n8k16.row.col.f32.f16.f16.f32 "
        "{%0,%1,%2,%3}, {%4,%5,%6,%7}, {%8,%9}, {%0,%1,%2,%3};"
        : "+f"(c[0]), "+f"(c[1]), "+f"(c[2]), "+f"(c[3])
        : "r"(a[0]), "r"(a[1]), "r"(a[2]), "r"(a[3]), "r"(b[0]), "r"(b[1]));
}

// ---------------- conversion kernels ----------------------------------------
__global__ __launch_bounds__(256) void f2h(
    const float* __restrict__ in, __half* __restrict__ out, int n4)
{
    int i = blockIdx.x * 256 + threadIdx.x;
    if (i >= n4) return;
    float4 v = reinterpret_cast<const float4*>(in)[i];
    __half2 lo = __floats2half2_rn(v.x, v.y);
    __half2 hi = __floats2half2_rn(v.z, v.w);
    reinterpret_cast<uint2*>(out)[i] =
        make_uint2(*reinterpret_cast<uint32_t*>(&lo), *reinterpret_cast<uint32_t*>(&hi));
}

// (D,P) fp32 -> (P,D) half
__global__ __launch_bounds__(256) void transpose_h(
    const float* __restrict__ in, __half* __restrict__ out)
{
    __shared__ float t[32][33];
    int tx = threadIdx.x, ty = threadIdx.y;
    int x = blockIdx.x * 32 + tx;
    int y = blockIdx.y * 32 + ty;
#pragma unroll
    for (int j = 0; j < 32; j += 8)
        t[ty + j][tx] = in[(size_t)(y + j) * PP + x];
    __syncthreads();
    int x2 = blockIdx.y * 32 + tx;
    int y2 = blockIdx.x * 32 + ty;
#pragma unroll
    for (int j = 0; j < 32; j += 8)
        out[(size_t)(y2 + j) * DD + x2] = __float2half_rn(t[tx][ty + j]);
}

// ---------------- fp16 mma.sync NT GEMM, 256x128 CTA, 512 threads ------------
// C[m,n] = sum_k A[m,k] * B[n,k]; A,B half row-major (leading dims in halves).
// 16 warps in 4x4 grid; warp tile 64x32.
// MODE: 0 plain | 1 causal tile-skip + 1/32 scale on store | 2 K bound m0+256
// OUTH: 1 -> store half, 0 -> store float
#define BK 32
#define BM 256
#define BN 128
#define TILEA 20480            // 256 rows * 80 B
#define TILEB 10240            // 128 rows * 80 B
#define STAGEB 30720
#define SMEM_TOTAL 122880      // 4 stages

template <int MODE, int OUTH>
__global__ void __launch_bounds__(512, 1) gemm_nt_h(
    const __half* __restrict__ A, const __half* __restrict__ B, void* __restrict__ Cv,
    int lda, int ldb, int ldc, int K,
    long long sA, long long sB, long long sC)
{
    const int m0 = blockIdx.y * BM;
    const int n0 = blockIdx.x * BN;
    if (MODE == 1 && n0 >= m0 + BM) return;   // tile fully above diagonal

    extern __shared__ char smem[];
    const int bz = blockIdx.z;
    A += (long long)bz * sA;
    B += (long long)bz * sB;

    const int tid = threadIdx.x;
    const int lane = tid & 31;
    const int wid = tid >> 5;
    const int warp_m = wid & 3;        // 4 x 64 rows
    const int warp_n = wid >> 2;       // 4 x 32 cols
    const int g = lane >> 2;           // 0..7
    const int t = lane & 3;            // 0..3

    const uint32_t smb = smem_u32(smem);

    int kend = K;
    if (MODE == 2) { int lim = m0 + BM; kend = (lim < K) ? lim : K; }
    const int T = kend / BK;

    float acc[4][4][4];                // 4 m16-tiles x 4 n8-tiles x 4
#pragma unroll
    for (int mt = 0; mt < 4; mt++)
#pragma unroll
        for (int nt = 0; nt < 4; nt++)
#pragma unroll
            for (int i = 0; i < 4; i++) acc[mt][nt][i] = 0.f;

    // loader: A 1024 chunks (2/thr) + B 512 chunks (1/thr), 16B each
    const int lrow = tid >> 2;          // 0..127
    const int lc4  = tid & 3;
    auto load_tile = [&](int kt) {
        const int k0 = kt * BK;
        const uint32_t dA = smb + (kt & 3) * STAGEB;
        const uint32_t dB = dA + TILEA;
#pragma unroll
        for (int i = 0; i < 2; i++) {
            int row = lrow + i * 128;   // 0..255
            CP_ASYNC16(dA + (uint32_t)(row * 80 + lc4 * 16),
                       &A[(long long)(m0 + row) * lda + k0 + lc4 * 8]);
        }
        CP_ASYNC16(dB + (uint32_t)(lrow * 80 + lc4 * 16),
                   &B[(long long)(n0 + lrow) * ldb + k0 + lc4 * 8]);
    };

#pragma unroll
    for (int p = 0; p < 3; p++) { if (p < T) load_tile(p); CP_COMMIT(); }

    const int lr = lane & 15;
    const int lcb = (lane >> 4) * 16;
    const uint32_t aRow = (uint32_t)((warp_m * 64 + lr) * 80) + lcb;
    const uint32_t bRow = (uint32_t)((warp_n * 32 + lr) * 80) + lcb;

    for (int kt = 0; kt < T; kt++) {
        CP_WAIT(2);
        __syncthreads();
        if (kt + 3 < T) load_tile(kt + 3);
        CP_COMMIT();

        const uint32_t bufA = smb + (kt & 3) * STAGEB;
        const uint32_t bufB = bufA + TILEA;

#pragma unroll
        for (int ks = 0; ks < BK; ks += 16) {
            uint32_t a[4][4];
#pragma unroll
            for (int mt = 0; mt < 4; mt++)
                LDSM_X4(a[mt][0], a[mt][1], a[mt][2], a[mt][3],
                        bufA + aRow + (uint32_t)(mt * 16 * 80 + ks * 2));
            uint32_t b[4][2];
#pragma unroll
            for (int p = 0; p < 2; p++) {
                uint32_t r0, r1, r2, r3;
                LDSM_X4(r0, r1, r2, r3,
                        bufB + bRow + (uint32_t)(p * 16 * 80 + ks * 2));
                b[2*p][0] = r0; b[2*p+1][0] = r1;
                b[2*p][1] = r2; b[2*p+1][1] = r3;
            }
#pragma unroll
            for (int mt = 0; mt < 4; mt++)
#pragma unroll
                for (int nt = 0; nt < 4; nt++)
                    mma_f16(acc[mt][nt], a[mt], b[nt]);
        }
    }

    // ---- epilogue ----
    if (OUTH) {
        __half* C = reinterpret_cast<__half*>(Cv) + (long long)bz * sC;
#pragma unroll
        for (int mt = 0; mt < 4; mt++) {
            long long r = m0 + warp_m * 64 + mt * 16 + g;
#pragma unroll
            for (int nt = 0; nt < 4; nt++) {
                int c = n0 + warp_n * 32 + nt * 8 + t * 2;
                *reinterpret_cast<__half2*>(&C[r * ldc + c]) =
                    __floats2half2_rn(acc[mt][nt][0], acc[mt][nt][1]);
                *reinterpret_cast<__half2*>(&C[(r + 8) * ldc + c]) =
                    __floats2half2_rn(acc[mt][nt][2], acc[mt][nt][3]);
            }
        }
    } else {
        const float sc = (MODE == 1) ? 0.03125f : 1.0f;
        float* C = reinterpret_cast<float*>(Cv) + (long long)bz * sC;
#pragma unroll
        for (int mt = 0; mt < 4; mt++) {
            long long r = m0 + warp_m * 64 + mt * 16 + g;
#pragma unroll
            for (int nt = 0; nt < 4; nt++) {
                int c = n0 + warp_n * 32 + nt * 8 + t * 2;
                *reinterpret_cast<float2*>(&C[r * ldc + c]) =
                    make_float2(acc[mt][nt][0] * sc, acc[mt][nt][1] * sc);
                *reinterpret_cast<float2*>(&C[(r + 8) * ldc + c]) =
                    make_float2(acc[mt][nt][2] * sc, acc[mt][nt][3] * sc);
            }
        }
    }
}

// ---------------- register-resident causal softmax ---------------------------
// Scores pre-scaled by 1/32. Zero tail to 256 boundary (context kend = m0+256).
__global__ __launch_bounds__(256) void softmax_causal(
    const float* __restrict__ Sc, __half* __restrict__ Ph)
{
    const int r = blockIdx.x;
    const int b = r >> 11;
    const int s = r & 2047;
    const float* row = Sc + ((size_t)b * SS + s) * SS;
    __half* prow = Ph + ((size_t)b * SS + s) * SS;
    const int L = s + 1;
    const int Lpad = (L + 255) & ~255;
    const int tid = threadIdx.x;
    const int lane = tid & 31;
    const int wid = tid >> 5;
    __shared__ float red[8];

    float v[8];
    float mx = -1e30f;
#pragma unroll
    for (int j = 0; j < 2; j++) {
        int base = (tid + 256 * j) * 4;
        if (base < L) {
            float4 tv = *reinterpret_cast<const float4*>(row + base);
            v[j*4+0] = tv.x; v[j*4+1] = tv.y; v[j*4+2] = tv.z; v[j*4+3] = tv.w;
#pragma unroll
            for (int e = 0; e < 4; e++)
                if (base + e < L) mx = fmaxf(mx, v[j*4+e]);
        }
    }
#pragma unroll
    for (int o = 16; o > 0; o >>= 1)
        mx = fmaxf(mx, __shfl_xor_sync(0xffffffffu, mx, o));
    if (lane == 0) red[wid] = mx;
    __syncthreads();
    if (wid == 0) {
        float m = red[lane & 7];
#pragma unroll
        for (int o = 4; o > 0; o >>= 1)
            m = fmaxf(m, __shfl_xor_sync(0xffffffffu, m, o));
        if (lane == 0) red[0] = m;
    }
    __syncthreads();
    mx = red[0];

    float sum = 0.f;
#pragma unroll
    for (int j = 0; j < 2; j++) {
        int base = (tid + 256 * j) * 4;
        if (base < L) {
#pragma unroll
            for (int e = 0; e < 4; e++) {
                float ev = (base + e < L) ? __expf(v[j*4+e] - mx) : 0.f;
                v[j*4+e] = ev;
                sum += ev;
            }
        }
    }
#pragma unroll
    for (int o = 16; o > 0; o >>= 1)
        sum += __shfl_xor_sync(0xffffffffu, sum, o);
    __syncthreads();
    if (lane == 0) red[wid] = sum;
    __syncthreads();
    if (wid == 0) {
        float m = red[lane & 7];
#pragma unroll
        for (int o = 4; o > 0; o >>= 1)
            m += __shfl_xor_sync(0xffffffffu, m, o);
        if (lane == 0) red[0] = m;
    }
    __syncthreads();
    const float inv = 1.f / red[0];

#pragma unroll
    for (int j = 0; j < 2; j++) {
        int base = (tid + 256 * j) * 4;
        if (base < Lpad) {
            float e0 = (base < L) ? v[j*4+0] * inv : 0.f;
            float e1 = (base + 1 < L) ? v[j*4+1] * inv : 0.f;
            float e2 = (base + 2 < L) ? v[j*4+2] * inv : 0.f;
            float e3 = (base + 3 < L) ? v[j*4+3] * inv : 0.f;
            __half2 lo = __floats2half2_rn(e0, e1);
            __half2 hi = __floats2half2_rn(e2, e3);
            *reinterpret_cast<uint2*>(prow + base) =
                make_uint2(*reinterpret_cast<uint32_t*>(&lo),
                           *reinterpret_cast<uint32_t*>(&hi));
        }
    }
}

// ---------------- driver ----------------------------------------------------
extern "C" void kernel_launch(void* const* d_in, const int* in_sizes, int n_in,
                              void* d_out, int out_size)
{
    const float* x  = (const float*)d_in[0];
    const float* Wq = (const float*)d_in[1];
    const float* Wk = (const float*)d_in[2];
    const float* Wv = (const float*)d_in[3];
    float* out = (float*)d_out;

    __half *qkh, *vt, *ph, *xh, *wt;
    float* sc;
    cudaGetSymbolAddress((void**)&qkh, g_qkh);
    cudaGetSymbolAddress((void**)&vt,  g_vt);
    cudaGetSymbolAddress((void**)&sc,  g_s);
    cudaGetSymbolAddress((void**)&ph,  g_ph);
    cudaGetSymbolAddress((void**)&xh,  g_xh);
    cudaGetSymbolAddress((void**)&wt,  g_wt);
    __half* wvt = wt + (size_t)2 * PP * DD;

    cudaFuncSetAttribute(gemm_nt_h<0,1>, cudaFuncAttributeMaxDynamicSharedMemorySize, SMEM_TOTAL);
    cudaFuncSetAttribute(gemm_nt_h<1,0>, cudaFuncAttributeMaxDynamicSharedMemorySize, SMEM_TOTAL);
    cudaFuncSetAttribute(gemm_nt_h<2,0>, cudaFuncAttributeMaxDynamicSharedMemorySize, SMEM_TOTAL);

    // 0) conversions
    const int xn4 = (BB * SS * DD) / 4;
    f2h<<<(xn4 + 255) / 256, 256>>>(x, xh, xn4);
    dim3 tb(32, 8), tg(32, 32);
    transpose_h<<<tg, tb>>>(Wq, wt);
    transpose_h<<<tg, tb>>>(Wk, wt + (size_t)PP * DD);
    transpose_h<<<tg, tb>>>(Wv, wvt);

    const long long sSD  = (long long)SS * DD;
    const long long sPS  = (long long)PP * SS;
    const long long sSSq = (long long)SS * SS;
    const long long sQK  = (long long)SS * 2048;
    const long long sSP  = (long long)SS * PP;

    // 1) fused q|k: NT(xh, [Wq^T;Wk^T])  M=B*S, N=2048, K=D
    dim3 gqk(2048 / BN, (BB * SS) / BM, 1);
    gemm_nt_h<0,1><<<gqk, 512, SMEM_TOTAL>>>(xh, wt, qkh, DD, DD, 2048, DD, 0, 0, 0);

    // 2) v^T per batch: NT(Wv^T, xh_b)  M=P, N=S, K=D
    dim3 gv(SS / BN, PP / BM, BB);
    gemm_nt_h<0,1><<<gv, 512, SMEM_TOTAL>>>(wvt, xh, vt, DD, DD, SS, DD, 0, sSD, sPS);

    // 3) scores: NT(q_b, k_b) strided views of qkh; 1/32 folded into store
    dim3 gs(SS / BN, SS / BM, BB);
    gemm_nt_h<1,0><<<gs, 512, SMEM_TOTAL>>>(qkh, qkh + 1024, sc,
                                            2048, 2048, SS, PP, sQK, sQK, sSSq);

    // 4) softmax, half probs + zero tail to 256 boundary
    softmax_causal<<<BB * SS, 256>>>(sc, ph);

    // 5) context: NT(P_b, v^T_b)  M=S, N=P, K bounded at m0+256
    dim3 gc(PP / BN, SS / BM, BB);
    gemm_nt_h<2,0><<<gc, 512, SMEM_TOTAL>>>(ph, vt, out, SS, SS, PP, SS, sSSq, sPS, sSP);
}